// round 11
// baseline (speedup 1.0000x reference)
#include <cuda_runtime.h>
#include <cuda_fp16.h>
#include <math.h>
#include <float.h>
#include <cstdint>

#define D_MODEL  1024
#define N_HEADS  16
#define HEAD_DIM 64
#define BATCH    2
#define SEQ      2048
#define M_TOT    (BATCH * SEQ)     // 4096
#define N_QKV    (3 * D_MODEL)     // 3072

// ---------------- scratch (allocation-free rule: __device__ globals) --------
__device__ __half g_qkv[(size_t)M_TOT * N_QKV];
__device__ __half g_x[(size_t)M_TOT * D_MODEL];
__device__ __half g_wq[(size_t)N_QKV * D_MODEL];
__device__ __half g_wo[(size_t)D_MODEL * D_MODEL];
__device__ __half g_att[(size_t)M_TOT * D_MODEL];

// ---------------- helpers ---------------------------------------------------
__device__ __forceinline__ uint32_t smem_u32(const void* p) {
    uint32_t a;
    asm("{ .reg .u64 t; cvta.to.shared.u64 t, %1; cvt.u32.u64 %0, t; }"
        : "=r"(a) : "l"(p));
    return a;
}
__device__ __forceinline__ void cp_async16(uint32_t dst, const void* src) {
    asm volatile("cp.async.cg.shared.global [%0], [%1], 16;" :: "r"(dst), "l"(src)
                 : "memory");
}
__device__ __forceinline__ void ldsm_x4(uint32_t* r, uint32_t addr) {
    asm volatile("ldmatrix.sync.aligned.m8n8.x4.shared.b16 {%0,%1,%2,%3}, [%4];"
        : "=r"(r[0]), "=r"(r[1]), "=r"(r[2]), "=r"(r[3]) : "r"(addr));
}
__device__ __forceinline__ void ldsm_x4_t(uint32_t* r, uint32_t addr) {
    asm volatile("ldmatrix.sync.aligned.m8n8.x4.trans.shared.b16 {%0,%1,%2,%3}, [%4];"
        : "=r"(r[0]), "=r"(r[1]), "=r"(r[2]), "=r"(r[3]) : "r"(addr));
}
// fp32-accumulator HMMA (half rate; kept for out-proj precision)
__device__ __forceinline__ void mma16816(float* c, const uint32_t* a, const uint32_t* b) {
    asm volatile("mma.sync.aligned.m16n8k16.row.col.f32.f16.f16.f32 "
        "{%0,%1,%2,%3}, {%4,%5,%6,%7}, {%8,%9}, {%0,%1,%2,%3};"
        : "+f"(c[0]), "+f"(c[1]), "+f"(c[2]), "+f"(c[3])
        : "r"(a[0]), "r"(a[1]), "r"(a[2]), "r"(a[3]), "r"(b[0]), "r"(b[1]));
}
// fp16-accumulator HMMA (double rate)
__device__ __forceinline__ void mma16816h(uint32_t* d, const uint32_t* a, const uint32_t* b) {
    asm volatile("mma.sync.aligned.m16n8k16.row.col.f16.f16.f16.f16 "
        "{%0,%1}, {%2,%3,%4,%5}, {%6,%7}, {%0,%1};"
        : "+r"(d[0]), "+r"(d[1])
        : "r"(a[0]), "r"(a[1]), "r"(a[2]), "r"(a[3]), "r"(b[0]), "r"(b[1]));
}
__device__ __forceinline__ void promote_add(float* acc, const uint32_t* d) {
    float2 f0 = __half22float2(*(const __half2*)&d[0]);
    float2 f1 = __half22float2(*(const __half2*)&d[1]);
    acc[0] += f0.x; acc[1] += f0.y; acc[2] += f1.x; acc[3] += f1.y;
}
__device__ __forceinline__ void promote_set(float* acc, const uint32_t* d) {
    float2 f0 = __half22float2(*(const __half2*)&d[0]);
    float2 f1 = __half22float2(*(const __half2*)&d[1]);
    acc[0] = f0.x; acc[1] = f0.y; acc[2] = f1.x; acc[3] = f1.y;
}
__device__ __forceinline__ uint32_t pack2h(float a, float b) {
    __half2 h = __floats2half2_rn(a, b);
    return *(uint32_t*)&h;
}

#define SC2F 0.18033688011112042f   // 0.125 * log2(e)

// ---------------- fused fp32 -> fp16 rounding (x, qkv_w, out_w) -------------
__global__ void __launch_bounds__(256) round_all(
    const float2* __restrict__ x,  __half2* __restrict__ xo,  int nx,
    const float2* __restrict__ w1, __half2* __restrict__ w1o, int n1,
    const float2* __restrict__ w2, __half2* __restrict__ w2o, int n2)
{
    int i = blockIdx.x * blockDim.x + threadIdx.x;
    if (i < nx) {
        float2 v = x[i];
        xo[i] = __floats2half2_rn(v.x, v.y);
    } else if (i < nx + n1) {
        float2 v = w1[i - nx];
        w1o[i - nx] = __floats2half2_rn(v.x, v.y);
    } else if (i < nx + n1 + n2) {
        float2 v = w2[i - nx - n1];
        w2o[i - nx - n1] = __floats2half2_rn(v.x, v.y);
    }
}

// ---------------- GEMM common: 4 warps, 64x64 warp tile, BK=64, 3-stage -----
#define GTILE_B  (128 * 128)
#define GSTAGE_B (2 * GTILE_B)
#define GEMM_SMEM (3 * GSTAGE_B)

// QKV GEMM: fp16-accumulator chains (k=64) promoted to fp32 per chunk.
// Writes fp16; Q columns (col < D_MODEL) prescaled by SC2F.
__global__ void __launch_bounds__(128, 2) gemm_mma_h(
    const __half* __restrict__ A, const __half* __restrict__ B,
    const float* __restrict__ bias, __half* __restrict__ Ch, int N, int K)
{
    extern __shared__ char smem[];
    const uint32_t sbase = smem_u32(smem);
    const int t = threadIdx.x, lane = t & 31, wid = t >> 5;
    const int wm0 = (wid & 1) * 64, wn0 = (wid >> 1) * 64;
    const int m0 = blockIdx.y * 128, n0 = blockIdx.x * 128;

    auto load = [&](int c, int st) {
        uint32_t stg = sbase + st * GSTAGE_B;
#pragma unroll
        for (int i = 0; i < 16; i++) {
            int idx = t + i * 128;
            int tile = idx >> 10;
            int r = (idx >> 3) & 127;
            int s = idx & 7;
            int row0 = tile ? n0 : m0;
            const __half* src = tile ? B : A;
            uint32_t sw = r * 128 + (((s ^ (r & 7)) & 7) << 4);
            cp_async16(stg + tile * GTILE_B + sw,
                       src + (size_t)(row0 + r) * K + c * 64 + s * 8);
        }
        asm volatile("cp.async.commit_group;" ::: "memory");
    };

    float acc[32][4];
#pragma unroll
    for (int i = 0; i < 32; i++)
#pragma unroll
        for (int j = 0; j < 4; j++) acc[i][j] = 0.0f;

    const int l15 = lane & 15;
    const uint32_t arx = l15 & 7;
    uint32_t ar128[4];
#pragma unroll
    for (int mt = 0; mt < 4; mt++) ar128[mt] = (wm0 + 16 * mt + l15) * 128;
    const uint32_t brbase = wn0 + ((lane >> 4) << 3) + (lane & 7);
    const uint32_t brx = brbase & 7;
    const uint32_t bsel = (lane >> 3) & 1;

    const int NC = K / 64;
    load(0, 0);
    load(1, 1);

    for (int c = 0; c < NC; c++) {
        if (c + 1 < NC)
            asm volatile("cp.async.wait_group 1;" ::: "memory");
        else
            asm volatile("cp.async.wait_group 0;" ::: "memory");
        __syncthreads();
        if (c + 2 < NC) {
            int st2 = c + 2; st2 -= (st2 / 3) * 3;
            load(c + 2, st2);
        }

        int stidx = c; stidx -= (stidx / 3) * 3;
        const uint32_t stg = sbase + stidx * GSTAGE_B;

        // all A fragments for this chunk (4 mt x 4 kk)
        uint32_t af[4][4][4];
#pragma unroll
        for (int kk = 0; kk < 4; kk++) {
            const uint32_t colA = (((kk * 2 + (lane >> 4)) ^ arx) & 7) << 4;
#pragma unroll
            for (int mt = 0; mt < 4; mt++)
                ldsm_x4(af[mt][kk], stg + ar128[mt] + colA);
        }
#pragma unroll
        for (int nt2 = 0; nt2 < 4; nt2++) {
            uint32_t bf[4][4];
#pragma unroll
            for (int kk = 0; kk < 4; kk++) {
                const uint32_t bcol = (((kk * 2 + bsel) ^ brx) & 7) << 4;
                ldsm_x4(bf[kk], stg + GTILE_B + (brbase + nt2 * 16) * 128 + bcol);
            }
#pragma unroll
            for (int mt = 0; mt < 4; mt++)
#pragma unroll
                for (int half = 0; half < 2; half++) {
                    uint32_t d16[2] = {0u, 0u};
#pragma unroll
                    for (int kk = 0; kk < 4; kk++)
                        mma16816h(d16, af[mt][kk], bf[kk] + half * 2);
                    promote_add(acc[mt * 8 + nt2 * 2 + half], d16);
                }
        }
    }

    const int r0 = m0 + wm0 + (lane >> 2);
    const int c0l = (lane & 3) * 2;
#pragma unroll
    for (int mt = 0; mt < 4; mt++)
#pragma unroll
        for (int nt = 0; nt < 8; nt++) {
            const float* c4 = acc[mt * 8 + nt];
            int row = r0 + mt * 16;
            int col = n0 + wn0 + nt * 8 + c0l;
            float2 bi = *(const float2*)(bias + col);
            float v0 = c4[0] + bi.x, v1 = c4[1] + bi.y;
            float v2 = c4[2] + bi.x, v3 = c4[3] + bi.y;
            if (col < D_MODEL) { v0 *= SC2F; v1 *= SC2F; v2 *= SC2F; v3 *= SC2F; }
            *(uint32_t*)(Ch + (size_t)row * N + col) = pack2h(v0, v1);
            *(uint32_t*)(Ch + (size_t)(row + 8) * N + col) = pack2h(v2, v3);
        }
}

// Out-projection GEMM: fp32 accumulators (precision reserve), fp32 output.
__global__ void __launch_bounds__(128, 2) gemm_mma_f(
    const __half* __restrict__ A, const __half* __restrict__ B,
    const float* __restrict__ bias, float* __restrict__ C, int N, int K)
{
    extern __shared__ char smem[];
    const uint32_t sbase = smem_u32(smem);
    const int t = threadIdx.x, lane = t & 31, wid = t >> 5;
    const int wm0 = (wid & 1) * 64, wn0 = (wid >> 1) * 64;
    const int m0 = blockIdx.y * 128, n0 = blockIdx.x * 128;

    auto load = [&](int c, int st) {
        uint32_t stg = sbase + st * GSTAGE_B;
#pragma unroll
        for (int i = 0; i < 16; i++) {
            int idx = t + i * 128;
            int tile = idx >> 10;
            int r = (idx >> 3) & 127;
            int s = idx & 7;
            int row0 = tile ? n0 : m0;
            const __half* src = tile ? B : A;
            uint32_t sw = r * 128 + (((s ^ (r & 7)) & 7) << 4);
            cp_async16(stg + tile * GTILE_B + sw,
                       src + (size_t)(row0 + r) * K + c * 64 + s * 8);
        }
        asm volatile("cp.async.commit_group;" ::: "memory");
    };

    float acc[32][4];
#pragma unroll
    for (int i = 0; i < 32; i++)
#pragma unroll
        for (int j = 0; j < 4; j++) acc[i][j] = 0.0f;

    const int l15 = lane & 15;
    const uint32_t arx = l15 & 7;
    uint32_t ar128[4];
#pragma unroll
    for (int mt = 0; mt < 4; mt++) ar128[mt] = (wm0 + 16 * mt + l15) * 128;
    const uint32_t brbase = wn0 + ((lane >> 4) << 3) + (lane & 7);
    const uint32_t brx = brbase & 7;
    const uint32_t bsel = (lane >> 3) & 1;

    const int NC = K / 64;
    load(0, 0);
    load(1, 1);

    for (int c = 0; c < NC; c++) {
        if (c + 1 < NC)
            asm volatile("cp.async.wait_group 1;" ::: "memory");
        else
            asm volatile("cp.async.wait_group 0;" ::: "memory");
        __syncthreads();
        if (c + 2 < NC) {
            int st2 = c + 2; st2 -= (st2 / 3) * 3;
            load(c + 2, st2);
        }

        int stidx = c; stidx -= (stidx / 3) * 3;
        const uint32_t stg = sbase + stidx * GSTAGE_B;
#pragma unroll
        for (int kk = 0; kk < 4; kk++) {
            uint32_t af[4][4];
            const uint32_t sA = kk * 2 + (lane >> 4);
            const uint32_t colA = ((sA ^ arx) & 7) << 4;
#pragma unroll
            for (int mt = 0; mt < 4; mt++)
                ldsm_x4(af[mt], stg + ar128[mt] + colA);
            const uint32_t sB = kk * 2 + bsel;
            const uint32_t bcol = ((sB ^ brx) & 7) << 4;
#pragma unroll
            for (int nt2 = 0; nt2 < 4; nt2++) {
                uint32_t bh[4];
                ldsm_x4(bh, stg + GTILE_B + (brbase + nt2 * 16) * 128 + bcol);
#pragma unroll
                for (int mt = 0; mt < 4; mt++) {
                    mma16816(acc[mt * 8 + nt2 * 2], af[mt], bh);
                    mma16816(acc[mt * 8 + nt2 * 2 + 1], af[mt], bh + 2);
                }
            }
        }
    }

    const int r0 = m0 + wm0 + (lane >> 2);
    const int c0l = (lane & 3) * 2;
#pragma unroll
    for (int mt = 0; mt < 4; mt++)
#pragma unroll
        for (int nt = 0; nt < 8; nt++) {
            const float* c4 = acc[mt * 8 + nt];
            int row = r0 + mt * 16;
            int col = n0 + wn0 + nt * 8 + c0l;
            float2 bi = *(const float2*)(bias + col);
            *(float2*)(C + (size_t)row * N + col) =
                make_float2(c4[0] + bi.x, c4[1] + bi.y);
            *(float2*)(C + (size_t)(row + 8) * N + col) =
                make_float2(c4[2] + bi.x, c4[3] + bi.y);
        }
}

// ---------------------------------------------------------------------------
// Split-KV-column causal flash attention; fp16-acc MMA chains.
// 128 thr (4 warps, 2x2). Q tile 64. Warp = 32 Q-rows x 32 KV-cols.
// ---------------------------------------------------------------------------
#define AQ_STR 72
#define AQ_TILE_B (64 * AQ_STR * 2)
#define AKV_TILE_B (64 * AQ_STR * 2)
#define AKV_STAGE_B (2 * AKV_TILE_B)
#define ATT_SMEM (AQ_TILE_B + 3 * AKV_STAGE_B)  // 64512

__global__ void __launch_bounds__(128, 3) flash_attn_mma(
    const __half* __restrict__ qkv, __half* __restrict__ att)
{
    extern __shared__ char smem[];
    const uint32_t sb = smem_u32(smem);
    const uint32_t ST0 = AQ_TILE_B;
    const int t = threadIdx.x, l = t & 31, w = t >> 5;
    const int wr = w >> 1, wc = w & 1;
    const int qt = (int)(gridDim.x - 1 - blockIdx.x);
    const int h = blockIdx.y, b = blockIdx.z;
    const int q0 = qt * 64;
    const size_t tok0 = (size_t)b * SEQ;
    const int NT = qt + 1;

#pragma unroll
    for (int it = 0; it < 4; it++) {
        int idx = t + it * 128;
        int r = idx >> 3, seg = idx & 7;
        size_t src = (tok0 + q0 + r) * N_QKV + h * HEAD_DIM + seg * 8;
        cp_async16(sb + (r * AQ_STR + seg * 8) * 2, qkv + src);
    }
    asm volatile("cp.async.commit_group;" ::: "memory");

    auto load_kv = [&](int kt, int s) {
        uint32_t stg = sb + ST0 + s * AKV_STAGE_B;
        int k0 = kt * 64;
#pragma unroll
        for (int it = 0; it < 4; it++) {
            int idx = t + it * 128;
            int r = idx >> 3, seg = idx & 7;
            size_t srcK = (tok0 + k0 + r) * N_QKV + D_MODEL + h * HEAD_DIM + seg * 8;
            uint32_t dst = (r * AQ_STR + seg * 8) * 2;
            cp_async16(stg + dst, qkv + srcK);
            cp_async16(stg + AKV_TILE_B + dst, qkv + srcK + D_MODEL);
        }
        asm volatile("cp.async.commit_group;" ::: "memory");
    };

    load_kv(0, 0);
    if (NT > 1) {
        load_kv(1, 1);
        asm volatile("cp.async.wait_group 2;" ::: "memory");
    } else {
        asm volatile("cp.async.wait_group 1;" ::: "memory");
    }
    __syncthreads();

    uint32_t qf[2][4][4];
#pragma unroll
    for (int mt = 0; mt < 2; mt++)
#pragma unroll
        for (int ks = 0; ks < 4; ks++)
            ldsm_x4(qf[mt][ks],
                sb + ((32 * wr + 16 * mt + (l & 15)) * AQ_STR +
                      (l >> 4) * 8 + ks * 16) * 2);

    float M[4], L[4], o[2][8][4];
#pragma unroll
    for (int i = 0; i < 4; i++) { M[i] = -1e30f; L[i] = 0.f; }
#pragma unroll
    for (int mt = 0; mt < 2; mt++)
#pragma unroll
        for (int nt = 0; nt < 8; nt++)
#pragma unroll
            for (int j = 0; j < 4; j++) o[mt][nt][j] = 0.f;

    const int rowq = q0 + 32 * wr + (l >> 2);
    const int colw = 32 * wc + (l & 3) * 2;

    for (int kt = 0; kt < NT; kt++) {
        if (kt + 1 < NT)
            asm volatile("cp.async.wait_group 1;" ::: "memory");
        else
            asm volatile("cp.async.wait_group 0;" ::: "memory");
        __syncthreads();
        if (kt + 2 < NT) {
            int s2 = kt + 2; s2 -= (s2 / 3) * 3;
            load_kv(kt + 2, s2);
        }
        int si = kt; si -= (si / 3) * 3;
        const uint32_t stg = sb + ST0 + si * AKV_STAGE_B;

        // S = Q K^T, fp16 chain over the full 64-dim dot
        float sacc[2][4][4];
#pragma unroll
        for (int np = 0; np < 2; np++) {
            uint32_t bh[4][4];
#pragma unroll
            for (int ks = 0; ks < 4; ks++)
                ldsm_x4(bh[ks], stg +
                    ((32 * wc + np * 16 + ((l >> 4) << 3) + (l & 7)) * AQ_STR +
                     ((l >> 3) & 1) * 8 + ks * 16) * 2);
#pragma unroll
            for (int mt = 0; mt < 2; mt++)
#pragma unroll
                for (int half = 0; half < 2; half++) {
                    uint32_t d16[2] = {0u, 0u};
#pragma unroll
                    for (int ks = 0; ks < 4; ks++)
                        mma16816h(d16, qf[mt][ks], bh[ks] + half * 2);
                    promote_set(sacc[mt][2 * np + half], d16);
                }
        }

        const int k0 = kt * 64;
        if (kt == qt) {
#pragma unroll
            for (int mt = 0; mt < 2; mt++)
#pragma unroll
                for (int nt = 0; nt < 4; nt++)
#pragma unroll
                    for (int j = 0; j < 4; j++)
                        if ((k0 + colw + nt * 8 + (j & 1)) >
                            (rowq + mt * 16 + (j >> 1) * 8))
                            sacc[mt][nt][j] = -1e30f;
        }

#pragma unroll
        for (int mt = 0; mt < 2; mt++)
#pragma unroll
            for (int half = 0; half < 2; half++) {
                const int mi = mt * 2 + half;
                const int jb = half * 2;
                float mloc = -1e30f;
#pragma unroll
                for (int nt = 0; nt < 4; nt++)
                    mloc = fmaxf(mloc, fmaxf(sacc[mt][nt][jb], sacc[mt][nt][jb + 1]));
                mloc = fmaxf(mloc, __shfl_xor_sync(~0u, mloc, 1));
                mloc = fmaxf(mloc, __shfl_xor_sync(~0u, mloc, 2));
                float Mn = fmaxf(M[mi], mloc);
                float f = exp2f(M[mi] - Mn);
                float rs = 0.f;
#pragma unroll
                for (int nt = 0; nt < 4; nt++) {
                    float p0 = exp2f(sacc[mt][nt][jb] - Mn);
                    float p1 = exp2f(sacc[mt][nt][jb + 1] - Mn);
                    sacc[mt][nt][jb] = p0; sacc[mt][nt][jb + 1] = p1;
                    rs += p0 + p1;
                }
                rs += __shfl_xor_sync(~0u, rs, 1);
                rs += __shfl_xor_sync(~0u, rs, 2);
                L[mi] = L[mi] * f + rs;
                M[mi] = Mn;
#pragma unroll
                for (int nt = 0; nt < 8; nt++) {
                    o[mt][nt][jb] *= f;
                    o[mt][nt][jb + 1] *= f;
                }
            }

        // O += P V, fp16 chain over both kp (32 keys), promoted into fp32 o
        uint32_t ph[2][2][4];   // [kp][mt]
#pragma unroll
        for (int kp = 0; kp < 2; kp++)
#pragma unroll
            for (int mt = 0; mt < 2; mt++) {
                ph[kp][mt][0] = pack2h(sacc[mt][2 * kp][0], sacc[mt][2 * kp][1]);
                ph[kp][mt][1] = pack2h(sacc[mt][2 * kp][2], sacc[mt][2 * kp][3]);
                ph[kp][mt][2] = pack2h(sacc[mt][2 * kp + 1][0], sacc[mt][2 * kp + 1][1]);
                ph[kp][mt][3] = pack2h(sacc[mt][2 * kp + 1][2], sacc[mt][2 * kp + 1][3]);
            }
#pragma unroll
        for (int np = 0; np < 4; np++) {
            uint32_t vh[2][4];
#pragma unroll
            for (int kp = 0; kp < 2; kp++)
                ldsm_x4_t(vh[kp], stg + AKV_TILE_B +
                    ((32 * wc + kp * 16 + (l & 15)) * AQ_STR +
                     np * 16 + (l >> 4) * 8) * 2);
#pragma unroll
            for (int mt = 0; mt < 2; mt++)
#pragma unroll
                for (int half = 0; half < 2; half++) {
                    uint32_t d16[2] = {0u, 0u};
#pragma unroll
                    for (int kp = 0; kp < 2; kp++)
                        mma16816h(d16, ph[kp][mt], vh[kp] + half * 2);
                    promote_add(o[mt][2 * np + half], d16);
                }
        }
    }

    // ---- merge the two KV-col groups ----
    __syncthreads();
    const int OSTR = 65;
    const uint32_t mboff = wr * (32 * OSTR * 4 + 1024);
    if (wc == 1) {
#pragma unroll
        for (int mt = 0; mt < 2; mt++)
#pragma unroll
            for (int nt = 0; nt < 8; nt++)
#pragma unroll
                for (int j = 0; j < 4; j++) {
                    int idx = mt * 32 + nt * 4 + j;
                    *(float*)(smem + mboff + (l * OSTR + idx) * 4) = o[mt][nt][j];
                }
#pragma unroll
        for (int i = 0; i < 4; i++) {
            *(float*)(smem + mboff + 32 * OSTR * 4 + l * 32 + i * 4) = M[i];
            *(float*)(smem + mboff + 32 * OSTR * 4 + l * 32 + 16 + i * 4) = L[i];
        }
    }
    __syncthreads();
    if (wc == 0) {
        float w0s[4], w1s[4], inv[4];
#pragma unroll
        for (int i = 0; i < 4; i++) {
            float M1 = *(float*)(smem + mboff + 32 * OSTR * 4 + l * 32 + i * 4);
            float L1 = *(float*)(smem + mboff + 32 * OSTR * 4 + l * 32 + 16 + i * 4);
            float Mx = fmaxf(M[i], M1);
            w0s[i] = exp2f(M[i] - Mx);
            w1s[i] = exp2f(M1 - Mx);
            inv[i] = 1.f / (L[i] * w0s[i] + L1 * w1s[i]);
        }
#pragma unroll
        for (int mt = 0; mt < 2; mt++)
#pragma unroll
            for (int nt = 0; nt < 8; nt++) {
                float v[4];
#pragma unroll
                for (int j = 0; j < 4; j++) {
                    int idx = mt * 32 + nt * 4 + j;
                    float o1 = *(float*)(smem + mboff + (l * OSTR + idx) * 4);
                    int mi = mt * 2 + (j >> 1);
                    v[j] = (o[mt][nt][j] * w0s[mi] + o1 * w1s[mi]) * inv[mi];
                }
                int col = h * HEAD_DIM + nt * 8 + (l & 3) * 2;
                size_t r0 = (tok0 + q0 + 32 * wr + mt * 16 + (l >> 2)) * D_MODEL + col;
                *(uint32_t*)(att + r0) = pack2h(v[0], v[1]);
                *(uint32_t*)(att + r0 + 8 * D_MODEL) = pack2h(v[2], v[3]);
            }
    }
}

// ---------------------------------------------------------------------------
extern "C" void kernel_launch(void* const* d_in, const int* in_sizes, int n_in,
                              void* d_out, int out_size)
{
    const float* x     = (const float*)d_in[0];
    const float* qkv_w = (const float*)d_in[1];
    const float* qkv_b = (const float*)d_in[2];
    const float* out_w = (const float*)d_in[3];
    const float* out_b = (const float*)d_in[4];
    float* out = (float*)d_out;

    __half *qkv, *xh, *wq, *wo, *att;
    cudaGetSymbolAddress((void**)&qkv, g_qkv);
    cudaGetSymbolAddress((void**)&xh, g_x);
    cudaGetSymbolAddress((void**)&wq, g_wq);
    cudaGetSymbolAddress((void**)&wo, g_wo);
    cudaGetSymbolAddress((void**)&att, g_att);

    cudaFuncSetAttribute(gemm_mma_h, cudaFuncAttributeMaxDynamicSharedMemorySize,
                         GEMM_SMEM);
    cudaFuncSetAttribute(gemm_mma_f, cudaFuncAttributeMaxDynamicSharedMemorySize,
                         GEMM_SMEM);
    cudaFuncSetAttribute(flash_attn_mma, cudaFuncAttributeMaxDynamicSharedMemorySize,
                         ATT_SMEM);

    int n2x = M_TOT * D_MODEL / 2;
    int n2q = N_QKV * D_MODEL / 2;
    int n2o = D_MODEL * D_MODEL / 2;
    int n2tot = n2x + n2q + n2o;
    round_all<<<(n2tot + 255) / 256, 256>>>(
        (const float2*)x, (__half2*)xh, n2x,
        (const float2*)qkv_w, (__half2*)wq, n2q,
        (const float2*)out_w, (__half2*)wo, n2o);

    // 1) QKV projection -> fp16 (Q columns pre-scaled), fp16-acc HMMA
    gemm_mma_h<<<dim3(N_QKV / 128, M_TOT / 128), 128, GEMM_SMEM>>>(
        xh, wq, qkv_b, qkv, N_QKV, D_MODEL);

    // 2) Split-KV-column causal flash attention -> fp16, fp16-acc HMMA
    flash_attn_mma<<<dim3(SEQ / 64, N_HEADS, BATCH), 128, ATT_SMEM>>>(qkv, att);

    // 3) Output projection -> fp32 final, fp32-acc HMMA (precision reserve)
    gemm_mma_f<<<dim3(D_MODEL / 128, M_TOT / 128), 128, GEMM_SMEM>>>(
        att, wo, out_b, out, D_MODEL, D_MODEL);
}

// round 12
// speedup vs baseline: 1.1601x; 1.1601x over previous
#include <cuda_runtime.h>
#include <cuda_fp16.h>
#include <math.h>
#include <float.h>
#include <cstdint>

#define D_MODEL  1024
#define N_HEADS  16
#define HEAD_DIM 64
#define BATCH    2
#define SEQ      2048
#define M_TOT    (BATCH * SEQ)     // 4096
#define N_QKV    (3 * D_MODEL)     // 3072

// ---------------- scratch (allocation-free rule: __device__ globals) --------
__device__ __half g_qkv[(size_t)M_TOT * N_QKV];
__device__ __half g_x[(size_t)M_TOT * D_MODEL];
__device__ __half g_wq[(size_t)N_QKV * D_MODEL];
__device__ __half g_wo[(size_t)D_MODEL * D_MODEL];
__device__ __half g_att[(size_t)M_TOT * D_MODEL];

// ---------------- helpers ---------------------------------------------------
__device__ __forceinline__ uint32_t smem_u32(const void* p) {
    uint32_t a;
    asm("{ .reg .u64 t; cvta.to.shared.u64 t, %1; cvt.u32.u64 %0, t; }"
        : "=r"(a) : "l"(p));
    return a;
}
__device__ __forceinline__ void cp_async16(uint32_t dst, const void* src) {
    asm volatile("cp.async.cg.shared.global [%0], [%1], 16;" :: "r"(dst), "l"(src)
                 : "memory");
}
__device__ __forceinline__ void ldsm_x4(uint32_t* r, uint32_t addr) {
    asm volatile("ldmatrix.sync.aligned.m8n8.x4.shared.b16 {%0,%1,%2,%3}, [%4];"
        : "=r"(r[0]), "=r"(r[1]), "=r"(r[2]), "=r"(r[3]) : "r"(addr));
}
__device__ __forceinline__ void ldsm_x4_t(uint32_t* r, uint32_t addr) {
    asm volatile("ldmatrix.sync.aligned.m8n8.x4.trans.shared.b16 {%0,%1,%2,%3}, [%4];"
        : "=r"(r[0]), "=r"(r[1]), "=r"(r[2]), "=r"(r[3]) : "r"(addr));
}
__device__ __forceinline__ void mma16816(float* c, const uint32_t* a, const uint32_t* b) {
    asm volatile("mma.sync.aligned.m16n8k16.row.col.f32.f16.f16.f32 "
        "{%0,%1,%2,%3}, {%4,%5,%6,%7}, {%8,%9}, {%0,%1,%2,%3};"
        : "+f"(c[0]), "+f"(c[1]), "+f"(c[2]), "+f"(c[3])
        : "r"(a[0]), "r"(a[1]), "r"(a[2]), "r"(a[3]), "r"(b[0]), "r"(b[1]));
}
__device__ __forceinline__ uint32_t pack2h(float a, float b) {
    __half2 h = __floats2half2_rn(a, b);
    return *(uint32_t*)&h;
}

#define SC2F 0.18033688011112042f   // 0.125 * log2(e)

// ---------------- fused fp32 -> fp16 rounding (x, qkv_w, out_w) -------------
__global__ void __launch_bounds__(256) round_all(
    const float2* __restrict__ x,  __half2* __restrict__ xo,  int nx,
    const float2* __restrict__ w1, __half2* __restrict__ w1o, int n1,
    const float2* __restrict__ w2, __half2* __restrict__ w2o, int n2)
{
    int i = blockIdx.x * blockDim.x + threadIdx.x;
    if (i < nx) {
        float2 v = x[i];
        xo[i] = __floats2half2_rn(v.x, v.y);
    } else if (i < nx + n1) {
        float2 v = w1[i - nx];
        w1o[i - nx] = __floats2half2_rn(v.x, v.y);
    } else if (i < nx + n1 + n2) {
        float2 v = w2[i - nx - n1];
        w2o[i - nx - n1] = __floats2half2_rn(v.x, v.y);
    }
}

// ---------------- mma.sync fp16 GEMM: 4 warps, 64x64 warp tile --------------
// C[m,n] = sum_k A[m,k]*B[n,k] + bias[n].  A,B K-major fp16, BK=64, 3-stage.
// mode: 0 = fp32 C;  2 = fp16 Ch, with cols < D_MODEL prescaled by SC2F (Q).
#define GTILE_B  (128 * 128)
#define GSTAGE_B (2 * GTILE_B)
#define GEMM_SMEM (3 * GSTAGE_B)

__global__ void __launch_bounds__(128, 2) gemm_mma(
    const __half* __restrict__ A, const __half* __restrict__ B,
    const float* __restrict__ bias, float* __restrict__ C,
    __half* __restrict__ Ch, int N, int K, int mode)
{
    extern __shared__ char smem[];
    const uint32_t sbase = smem_u32(smem);
    const int t = threadIdx.x, lane = t & 31, wid = t >> 5;
    const int wm0 = (wid & 1) * 64, wn0 = (wid >> 1) * 64;
    const int m0 = blockIdx.y * 128, n0 = blockIdx.x * 128;

    auto load = [&](int c, int st) {
        uint32_t stg = sbase + st * GSTAGE_B;
#pragma unroll
        for (int i = 0; i < 16; i++) {
            int idx = t + i * 128;            // 0..2047: [tile 2][row 128][seg 8]
            int tile = idx >> 10;
            int r = (idx >> 3) & 127;
            int s = idx & 7;
            int row0 = tile ? n0 : m0;
            const __half* src = tile ? B : A;
            uint32_t sw = r * 128 + (((s ^ (r & 7)) & 7) << 4);
            cp_async16(stg + tile * GTILE_B + sw,
                       src + (size_t)(row0 + r) * K + c * 64 + s * 8);
        }
        asm volatile("cp.async.commit_group;" ::: "memory");
    };

    float acc[32][4];
#pragma unroll
    for (int i = 0; i < 32; i++)
#pragma unroll
        for (int j = 0; j < 4; j++) acc[i][j] = 0.0f;

    const int l15 = lane & 15;
    const uint32_t arx = l15 & 7;
    uint32_t ar128[4];
#pragma unroll
    for (int mt = 0; mt < 4; mt++) ar128[mt] = (wm0 + 16 * mt + l15) * 128;
    const uint32_t brbase = wn0 + ((lane >> 4) << 3) + (lane & 7);
    const uint32_t brx = brbase & 7;
    const uint32_t bsel = (lane >> 3) & 1;

    const int NC = K / 64;
    load(0, 0);
    load(1, 1);

    int st = 0, pst = 2;   // ring counters: current stage, prefetch stage
    for (int c = 0; c < NC; c++) {
        if (c + 1 < NC)
            asm volatile("cp.async.wait_group 1;" ::: "memory");
        else
            asm volatile("cp.async.wait_group 0;" ::: "memory");
        __syncthreads();
        if (c + 2 < NC) load(c + 2, pst);

        const uint32_t stg = sbase + st * GSTAGE_B;
#pragma unroll
        for (int kk = 0; kk < 4; kk++) {
            uint32_t af[4][4];
            const uint32_t sA = kk * 2 + (lane >> 4);
            const uint32_t colA = ((sA ^ arx) & 7) << 4;
#pragma unroll
            for (int mt = 0; mt < 4; mt++)
                ldsm_x4(af[mt], stg + ar128[mt] + colA);
            const uint32_t sB = kk * 2 + bsel;
            const uint32_t bcol = ((sB ^ brx) & 7) << 4;
#pragma unroll
            for (int nt2 = 0; nt2 < 4; nt2++) {
                uint32_t bh[4];
                ldsm_x4(bh, stg + GTILE_B + (brbase + nt2 * 16) * 128 + bcol);
#pragma unroll
                for (int mt = 0; mt < 4; mt++) {
                    mma16816(acc[mt * 8 + nt2 * 2], af[mt], bh);
                    mma16816(acc[mt * 8 + nt2 * 2 + 1], af[mt], bh + 2);
                }
            }
        }
        st++;  if (st == 3)  st = 0;
        pst++; if (pst == 3) pst = 0;
    }

    const int r0 = m0 + wm0 + (lane >> 2);
    const int c0l = (lane & 3) * 2;
#pragma unroll
    for (int mt = 0; mt < 4; mt++)
#pragma unroll
        for (int nt = 0; nt < 8; nt++) {
            const float* c4 = acc[mt * 8 + nt];
            int row = r0 + mt * 16;
            int col = n0 + wn0 + nt * 8 + c0l;
            float2 bi = *(const float2*)(bias + col);
            float v0 = c4[0] + bi.x, v1 = c4[1] + bi.y;
            float v2 = c4[2] + bi.x, v3 = c4[3] + bi.y;
            if (mode == 0) {
                *(float2*)(C + (size_t)row * N + col) = make_float2(v0, v1);
                *(float2*)(C + (size_t)(row + 8) * N + col) = make_float2(v2, v3);
            } else {
                if (col < D_MODEL) {   // Q columns: fold softmax scale (log2 dom)
                    v0 *= SC2F; v1 *= SC2F; v2 *= SC2F; v3 *= SC2F;
                }
                *(uint32_t*)(Ch + (size_t)row * N + col) = pack2h(v0, v1);
                *(uint32_t*)(Ch + (size_t)(row + 8) * N + col) = pack2h(v2, v3);
            }
        }
}

// ---------------------------------------------------------------------------
// Split-KV-column causal flash attention (Q pre-scaled; exp2 softmax).
// 128 thr (4 warps, 2x2). Q tile 64. Warp = 32 Q-rows x 32 KV-cols.
// ---------------------------------------------------------------------------
#define AQ_STR 72
#define AQ_TILE_B (64 * AQ_STR * 2)
#define AKV_TILE_B (64 * AQ_STR * 2)
#define AKV_STAGE_B (2 * AKV_TILE_B)
#define ATT_SMEM (AQ_TILE_B + 3 * AKV_STAGE_B)  // 64512

__global__ void __launch_bounds__(128, 3) flash_attn_mma(
    const __half* __restrict__ qkv, __half* __restrict__ att)
{
    extern __shared__ char smem[];
    const uint32_t sb = smem_u32(smem);
    const uint32_t ST0 = AQ_TILE_B;
    const int t = threadIdx.x, l = t & 31, w = t >> 5;
    const int wr = w >> 1, wc = w & 1;
    const int qt = (int)(gridDim.x - 1 - blockIdx.x);   // heavy tiles first
    const int h = blockIdx.y, b = blockIdx.z;
    const int q0 = qt * 64;
    const size_t tok0 = (size_t)b * SEQ;
    const int NT = qt + 1;

#pragma unroll
    for (int it = 0; it < 4; it++) {
        int idx = t + it * 128;
        int r = idx >> 3, seg = idx & 7;
        size_t src = (tok0 + q0 + r) * N_QKV + h * HEAD_DIM + seg * 8;
        cp_async16(sb + (r * AQ_STR + seg * 8) * 2, qkv + src);
    }
    asm volatile("cp.async.commit_group;" ::: "memory");

    auto load_kv = [&](int kt, int s) {
        uint32_t stg = sb + ST0 + s * AKV_STAGE_B;
        int k0 = kt * 64;
#pragma unroll
        for (int it = 0; it < 4; it++) {
            int idx = t + it * 128;
            int r = idx >> 3, seg = idx & 7;
            size_t srcK = (tok0 + k0 + r) * N_QKV + D_MODEL + h * HEAD_DIM + seg * 8;
            uint32_t dst = (r * AQ_STR + seg * 8) * 2;
            cp_async16(stg + dst, qkv + srcK);
            cp_async16(stg + AKV_TILE_B + dst, qkv + srcK + D_MODEL);
        }
        asm volatile("cp.async.commit_group;" ::: "memory");
    };

    load_kv(0, 0);
    if (NT > 1) {
        load_kv(1, 1);
        asm volatile("cp.async.wait_group 2;" ::: "memory");  // Q done
    } else {
        asm volatile("cp.async.wait_group 1;" ::: "memory");
    }
    __syncthreads();

    uint32_t qf[2][4][4];
#pragma unroll
    for (int mt = 0; mt < 2; mt++)
#pragma unroll
        for (int ks = 0; ks < 4; ks++)
            ldsm_x4(qf[mt][ks],
                sb + ((32 * wr + 16 * mt + (l & 15)) * AQ_STR +
                      (l >> 4) * 8 + ks * 16) * 2);

    float M[4], L[4], o[2][8][4];
#pragma unroll
    for (int i = 0; i < 4; i++) { M[i] = -1e30f; L[i] = 0.f; }
#pragma unroll
    for (int mt = 0; mt < 2; mt++)
#pragma unroll
        for (int nt = 0; nt < 8; nt++)
#pragma unroll
            for (int j = 0; j < 4; j++) o[mt][nt][j] = 0.f;

    const int rowq = q0 + 32 * wr + (l >> 2);
    const int colw = 32 * wc + (l & 3) * 2;

    // hoisted intra-stage offsets
    const uint32_t kboff = ((32 * wc + ((l >> 4) << 3) + (l & 7)) * AQ_STR +
                           ((l >> 3) & 1) * 8) * 2;
    const uint32_t vboff = ((32 * wc + (l & 15)) * AQ_STR + (l >> 4) * 8) * 2;

    int si = 0, ps = 2;   // ring counters
    for (int kt = 0; kt < NT; kt++) {
        if (kt + 1 < NT)
            asm volatile("cp.async.wait_group 1;" ::: "memory");
        else
            asm volatile("cp.async.wait_group 0;" ::: "memory");
        __syncthreads();
        if (kt + 2 < NT) load_kv(kt + 2, ps);
        const uint32_t stg = sb + ST0 + si * AKV_STAGE_B;

        float sacc[2][4][4];
#pragma unroll
        for (int mt = 0; mt < 2; mt++)
#pragma unroll
            for (int nt = 0; nt < 4; nt++)
#pragma unroll
                for (int j = 0; j < 4; j++) sacc[mt][nt][j] = 0.f;

#pragma unroll
        for (int ks = 0; ks < 4; ks++) {
#pragma unroll
            for (int np = 0; np < 2; np++) {
                uint32_t bh[4];
                ldsm_x4(bh, stg + kboff + (np * 16 * AQ_STR + ks * 16) * 2);
#pragma unroll
                for (int mt = 0; mt < 2; mt++) {
                    mma16816(sacc[mt][2 * np], qf[mt][ks], bh);
                    mma16816(sacc[mt][2 * np + 1], qf[mt][ks], bh + 2);
                }
            }
        }

        // causal mask only (S already in log2 domain via pre-scaled Q)
        const int k0 = kt * 64;
        if (kt == qt) {
#pragma unroll
            for (int mt = 0; mt < 2; mt++)
#pragma unroll
                for (int nt = 0; nt < 4; nt++)
#pragma unroll
                    for (int j = 0; j < 4; j++)
                        if ((k0 + colw + nt * 8 + (j & 1)) >
                            (rowq + mt * 16 + (j >> 1) * 8))
                            sacc[mt][nt][j] = -1e30f;
        }

#pragma unroll
        for (int mt = 0; mt < 2; mt++)
#pragma unroll
            for (int half = 0; half < 2; half++) {
                const int mi = mt * 2 + half;
                const int jb = half * 2;
                float mloc = -1e30f;
#pragma unroll
                for (int nt = 0; nt < 4; nt++)
                    mloc = fmaxf(mloc, fmaxf(sacc[mt][nt][jb], sacc[mt][nt][jb + 1]));
                mloc = fmaxf(mloc, __shfl_xor_sync(~0u, mloc, 1));
                mloc = fmaxf(mloc, __shfl_xor_sync(~0u, mloc, 2));
                float Mn = fmaxf(M[mi], mloc);
                float f = exp2f(M[mi] - Mn);
                float rs = 0.f;
#pragma unroll
                for (int nt = 0; nt < 4; nt++) {
                    float p0 = exp2f(sacc[mt][nt][jb] - Mn);
                    float p1 = exp2f(sacc[mt][nt][jb + 1] - Mn);
                    sacc[mt][nt][jb] = p0; sacc[mt][nt][jb + 1] = p1;
                    rs += p0 + p1;
                }
                rs += __shfl_xor_sync(~0u, rs, 1);
                rs += __shfl_xor_sync(~0u, rs, 2);
                L[mi] = L[mi] * f + rs;
                M[mi] = Mn;
#pragma unroll
                for (int nt = 0; nt < 8; nt++) {
                    o[mt][nt][jb] *= f;
                    o[mt][nt][jb + 1] *= f;
                }
            }

#pragma unroll
        for (int kp = 0; kp < 2; kp++) {
            uint32_t ph[2][4];
#pragma unroll
            for (int mt = 0; mt < 2; mt++) {
                ph[mt][0] = pack2h(sacc[mt][2 * kp][0], sacc[mt][2 * kp][1]);
                ph[mt][1] = pack2h(sacc[mt][2 * kp][2], sacc[mt][2 * kp][3]);
                ph[mt][2] = pack2h(sacc[mt][2 * kp + 1][0], sacc[mt][2 * kp + 1][1]);
                ph[mt][3] = pack2h(sacc[mt][2 * kp + 1][2], sacc[mt][2 * kp + 1][3]);
            }
#pragma unroll
            for (int np = 0; np < 4; np++) {
                uint32_t vh[4];
                ldsm_x4_t(vh, stg + AKV_TILE_B + vboff +
                          (kp * 16 * AQ_STR + np * 16) * 2);
#pragma unroll
                for (int mt = 0; mt < 2; mt++) {
                    mma16816(o[mt][2 * np], ph[mt], vh);
                    mma16816(o[mt][2 * np + 1], ph[mt], vh + 2);
                }
            }
        }
        si++; if (si == 3) si = 0;
        ps++; if (ps == 3) ps = 0;
    }

    // ---- merge the two KV-col groups ----
    __syncthreads();
    const int OSTR = 65;
    const uint32_t mboff = wr * (32 * OSTR * 4 + 1024);
    if (wc == 1) {
#pragma unroll
        for (int mt = 0; mt < 2; mt++)
#pragma unroll
            for (int nt = 0; nt < 8; nt++)
#pragma unroll
                for (int j = 0; j < 4; j++) {
                    int idx = mt * 32 + nt * 4 + j;
                    *(float*)(smem + mboff + (l * OSTR + idx) * 4) = o[mt][nt][j];
                }
#pragma unroll
        for (int i = 0; i < 4; i++) {
            *(float*)(smem + mboff + 32 * OSTR * 4 + l * 32 + i * 4) = M[i];
            *(float*)(smem + mboff + 32 * OSTR * 4 + l * 32 + 16 + i * 4) = L[i];
        }
    }
    __syncthreads();
    if (wc == 0) {
        float w0s[4], w1s[4], inv[4];
#pragma unroll
        for (int i = 0; i < 4; i++) {
            float M1 = *(float*)(smem + mboff + 32 * OSTR * 4 + l * 32 + i * 4);
            float L1 = *(float*)(smem + mboff + 32 * OSTR * 4 + l * 32 + 16 + i * 4);
            float Mx = fmaxf(M[i], M1);
            w0s[i] = exp2f(M[i] - Mx);
            w1s[i] = exp2f(M1 - Mx);
            inv[i] = 1.f / (L[i] * w0s[i] + L1 * w1s[i]);
        }
#pragma unroll
        for (int mt = 0; mt < 2; mt++)
#pragma unroll
            for (int nt = 0; nt < 8; nt++) {
                float v[4];
#pragma unroll
                for (int j = 0; j < 4; j++) {
                    int idx = mt * 32 + nt * 4 + j;
                    float o1 = *(float*)(smem + mboff + (l * OSTR + idx) * 4);
                    int mi = mt * 2 + (j >> 1);
                    v[j] = (o[mt][nt][j] * w0s[mi] + o1 * w1s[mi]) * inv[mi];
                }
                int col = h * HEAD_DIM + nt * 8 + (l & 3) * 2;
                size_t r0 = (tok0 + q0 + 32 * wr + mt * 16 + (l >> 2)) * D_MODEL + col;
                *(uint32_t*)(att + r0) = pack2h(v[0], v[1]);
                *(uint32_t*)(att + r0 + 8 * D_MODEL) = pack2h(v[2], v[3]);
            }
    }
}

// ---------------------------------------------------------------------------
extern "C" void kernel_launch(void* const* d_in, const int* in_sizes, int n_in,
                              void* d_out, int out_size)
{
    const float* x     = (const float*)d_in[0];
    const float* qkv_w = (const float*)d_in[1];
    const float* qkv_b = (const float*)d_in[2];
    const float* out_w = (const float*)d_in[3];
    const float* out_b = (const float*)d_in[4];
    float* out = (float*)d_out;

    __half *qkv, *xh, *wq, *wo, *att;
    cudaGetSymbolAddress((void**)&qkv, g_qkv);
    cudaGetSymbolAddress((void**)&xh, g_x);
    cudaGetSymbolAddress((void**)&wq, g_wq);
    cudaGetSymbolAddress((void**)&wo, g_wo);
    cudaGetSymbolAddress((void**)&att, g_att);

    cudaFuncSetAttribute(gemm_mma, cudaFuncAttributeMaxDynamicSharedMemorySize,
                         GEMM_SMEM);
    cudaFuncSetAttribute(flash_attn_mma, cudaFuncAttributeMaxDynamicSharedMemorySize,
                         ATT_SMEM);

    int n2x = M_TOT * D_MODEL / 2;
    int n2q = N_QKV * D_MODEL / 2;
    int n2o = D_MODEL * D_MODEL / 2;
    int n2tot = n2x + n2q + n2o;
    round_all<<<(n2tot + 255) / 256, 256>>>(
        (const float2*)x, (__half2*)xh, n2x,
        (const float2*)qkv_w, (__half2*)wq, n2q,
        (const float2*)out_w, (__half2*)wo, n2o);

    // 1) QKV projection -> fp16 (Q columns pre-scaled by 0.125*log2e)
    gemm_mma<<<dim3(N_QKV / 128, M_TOT / 128), 128, GEMM_SMEM>>>(
        xh, wq, qkv_b, nullptr, qkv, N_QKV, D_MODEL, 2);

    // 2) Split-KV-column causal flash attention -> fp16
    flash_attn_mma<<<dim3(SEQ / 64, N_HEADS, BATCH), 128, ATT_SMEM>>>(qkv, att);

    // 3) Output projection -> fp32 final
    gemm_mma<<<dim3(D_MODEL / 128, M_TOT / 128), 128, GEMM_SMEM>>>(
        att, wo, out_b, out, nullptr, D_MODEL, D_MODEL, 0);
}

// round 13
// speedup vs baseline: 1.2222x; 1.0535x over previous
#include <cuda_runtime.h>
#include <cuda_fp16.h>
#include <math.h>
#include <float.h>
#include <cstdint>

#define D_MODEL  1024
#define N_HEADS  16
#define HEAD_DIM 64
#define BATCH    2
#define SEQ      2048
#define M_TOT    (BATCH * SEQ)     // 4096
#define N_QKV    (3 * D_MODEL)     // 3072

// ---------------- scratch (allocation-free rule: __device__ globals) --------
__device__ __half g_qkv[(size_t)M_TOT * N_QKV];
__device__ __half g_x[(size_t)M_TOT * D_MODEL];
__device__ __half g_wq[(size_t)N_QKV * D_MODEL];
__device__ __half g_wo[(size_t)D_MODEL * D_MODEL];
__device__ __half g_att[(size_t)M_TOT * D_MODEL];

// ---------------- helpers ---------------------------------------------------
__device__ __forceinline__ uint32_t smem_u32(const void* p) {
    uint32_t a;
    asm("{ .reg .u64 t; cvta.to.shared.u64 t, %1; cvt.u32.u64 %0, t; }"
        : "=r"(a) : "l"(p));
    return a;
}
__device__ __forceinline__ void cp_async16(uint32_t dst, const void* src) {
    asm volatile("cp.async.cg.shared.global [%0], [%1], 16;" :: "r"(dst), "l"(src)
                 : "memory");
}
__device__ __forceinline__ void ldsm_x4(uint32_t* r, uint32_t addr) {
    asm volatile("ldmatrix.sync.aligned.m8n8.x4.shared.b16 {%0,%1,%2,%3}, [%4];"
        : "=r"(r[0]), "=r"(r[1]), "=r"(r[2]), "=r"(r[3]) : "r"(addr));
}
__device__ __forceinline__ void ldsm_x4_t(uint32_t* r, uint32_t addr) {
    asm volatile("ldmatrix.sync.aligned.m8n8.x4.trans.shared.b16 {%0,%1,%2,%3}, [%4];"
        : "=r"(r[0]), "=r"(r[1]), "=r"(r[2]), "=r"(r[3]) : "r"(addr));
}
__device__ __forceinline__ void mma16816(float* c, const uint32_t* a, const uint32_t* b) {
    asm volatile("mma.sync.aligned.m16n8k16.row.col.f32.f16.f16.f32 "
        "{%0,%1,%2,%3}, {%4,%5,%6,%7}, {%8,%9}, {%0,%1,%2,%3};"
        : "+f"(c[0]), "+f"(c[1]), "+f"(c[2]), "+f"(c[3])
        : "r"(a[0]), "r"(a[1]), "r"(a[2]), "r"(a[3]), "r"(b[0]), "r"(b[1]));
}
__device__ __forceinline__ uint32_t pack2h(float a, float b) {
    __half2 h = __floats2half2_rn(a, b);
    return *(uint32_t*)&h;
}
__device__ __forceinline__ uint32_t ex2_h2(uint32_t x) {
    uint32_t r;
    asm("ex2.approx.f16x2 %0, %1;" : "=r"(r) : "r"(x));
    return r;
}

#define SC2F 0.18033688011112042f   // 0.125 * log2(e)

// ---------------- fused fp32 -> fp16 rounding (x, qkv_w, out_w) -------------
__global__ void __launch_bounds__(256) round_all(
    const float2* __restrict__ x,  __half2* __restrict__ xo,  int nx,
    const float2* __restrict__ w1, __half2* __restrict__ w1o, int n1,
    const float2* __restrict__ w2, __half2* __restrict__ w2o, int n2)
{
    int i = blockIdx.x * blockDim.x + threadIdx.x;
    if (i < nx) {
        float2 v = x[i];
        xo[i] = __floats2half2_rn(v.x, v.y);
    } else if (i < nx + n1) {
        float2 v = w1[i - nx];
        w1o[i - nx] = __floats2half2_rn(v.x, v.y);
    } else if (i < nx + n1 + n2) {
        float2 v = w2[i - nx - n1];
        w2o[i - nx - n1] = __floats2half2_rn(v.x, v.y);
    }
}

// ---------------- mma.sync fp16 GEMM: 4 warps, 64x64 warp tile --------------
// (unchanged from round 12 — at the mma.sync plateau)
#define GTILE_B  (128 * 128)
#define GSTAGE_B (2 * GTILE_B)
#define GEMM_SMEM (3 * GSTAGE_B)

__global__ void __launch_bounds__(128, 2) gemm_mma(
    const __half* __restrict__ A, const __half* __restrict__ B,
    const float* __restrict__ bias, float* __restrict__ C,
    __half* __restrict__ Ch, int N, int K, int mode)
{
    extern __shared__ char smem[];
    const uint32_t sbase = smem_u32(smem);
    const int t = threadIdx.x, lane = t & 31, wid = t >> 5;
    const int wm0 = (wid & 1) * 64, wn0 = (wid >> 1) * 64;
    const int m0 = blockIdx.y * 128, n0 = blockIdx.x * 128;

    auto load = [&](int c, int st) {
        uint32_t stg = sbase + st * GSTAGE_B;
#pragma unroll
        for (int i = 0; i < 16; i++) {
            int idx = t + i * 128;
            int tile = idx >> 10;
            int r = (idx >> 3) & 127;
            int s = idx & 7;
            int row0 = tile ? n0 : m0;
            const __half* src = tile ? B : A;
            uint32_t sw = r * 128 + (((s ^ (r & 7)) & 7) << 4);
            cp_async16(stg + tile * GTILE_B + sw,
                       src + (size_t)(row0 + r) * K + c * 64 + s * 8);
        }
        asm volatile("cp.async.commit_group;" ::: "memory");
    };

    float acc[32][4];
#pragma unroll
    for (int i = 0; i < 32; i++)
#pragma unroll
        for (int j = 0; j < 4; j++) acc[i][j] = 0.0f;

    const int l15 = lane & 15;
    const uint32_t arx = l15 & 7;
    uint32_t ar128[4];
#pragma unroll
    for (int mt = 0; mt < 4; mt++) ar128[mt] = (wm0 + 16 * mt + l15) * 128;
    const uint32_t brbase = wn0 + ((lane >> 4) << 3) + (lane & 7);
    const uint32_t brx = brbase & 7;
    const uint32_t bsel = (lane >> 3) & 1;

    const int NC = K / 64;
    load(0, 0);
    load(1, 1);

    int st = 0, pst = 2;
    for (int c = 0; c < NC; c++) {
        if (c + 1 < NC)
            asm volatile("cp.async.wait_group 1;" ::: "memory");
        else
            asm volatile("cp.async.wait_group 0;" ::: "memory");
        __syncthreads();
        if (c + 2 < NC) load(c + 2, pst);

        const uint32_t stg = sbase + st * GSTAGE_B;
#pragma unroll
        for (int kk = 0; kk < 4; kk++) {
            uint32_t af[4][4];
            const uint32_t sA = kk * 2 + (lane >> 4);
            const uint32_t colA = ((sA ^ arx) & 7) << 4;
#pragma unroll
            for (int mt = 0; mt < 4; mt++)
                ldsm_x4(af[mt], stg + ar128[mt] + colA);
            const uint32_t sB = kk * 2 + bsel;
            const uint32_t bcol = ((sB ^ brx) & 7) << 4;
#pragma unroll
            for (int nt2 = 0; nt2 < 4; nt2++) {
                uint32_t bh[4];
                ldsm_x4(bh, stg + GTILE_B + (brbase + nt2 * 16) * 128 + bcol);
#pragma unroll
                for (int mt = 0; mt < 4; mt++) {
                    mma16816(acc[mt * 8 + nt2 * 2], af[mt], bh);
                    mma16816(acc[mt * 8 + nt2 * 2 + 1], af[mt], bh + 2);
                }
            }
        }
        st++;  if (st == 3)  st = 0;
        pst++; if (pst == 3) pst = 0;
    }

    const int r0 = m0 + wm0 + (lane >> 2);
    const int c0l = (lane & 3) * 2;
#pragma unroll
    for (int mt = 0; mt < 4; mt++)
#pragma unroll
        for (int nt = 0; nt < 8; nt++) {
            const float* c4 = acc[mt * 8 + nt];
            int row = r0 + mt * 16;
            int col = n0 + wn0 + nt * 8 + c0l;
            float2 bi = *(const float2*)(bias + col);
            float v0 = c4[0] + bi.x, v1 = c4[1] + bi.y;
            float v2 = c4[2] + bi.x, v3 = c4[3] + bi.y;
            if (mode == 0) {
                *(float2*)(C + (size_t)row * N + col) = make_float2(v0, v1);
                *(float2*)(C + (size_t)(row + 8) * N + col) = make_float2(v2, v3);
            } else {
                if (col < D_MODEL) {
                    v0 *= SC2F; v1 *= SC2F; v2 *= SC2F; v3 *= SC2F;
                }
                *(uint32_t*)(Ch + (size_t)row * N + col) = pack2h(v0, v1);
                *(uint32_t*)(Ch + (size_t)(row + 8) * N + col) = pack2h(v2, v3);
            }
        }
}

// ---------------------------------------------------------------------------
// Split-KV-column causal flash attention.
// NEW: fp16x2 exp (ex2.approx.f16x2) + row-sums via ones-MMA.
// ---------------------------------------------------------------------------
#define AQ_STR 72
#define AQ_TILE_B (64 * AQ_STR * 2)
#define AKV_TILE_B (64 * AQ_STR * 2)
#define AKV_STAGE_B (2 * AKV_TILE_B)
#define ATT_SMEM (AQ_TILE_B + 3 * AKV_STAGE_B)  // 64512

__global__ void __launch_bounds__(128, 3) flash_attn_mma(
    const __half* __restrict__ qkv, __half* __restrict__ att)
{
    extern __shared__ char smem[];
    const uint32_t sb = smem_u32(smem);
    const uint32_t ST0 = AQ_TILE_B;
    const int t = threadIdx.x, l = t & 31, w = t >> 5;
    const int wr = w >> 1, wc = w & 1;
    const int qt = (int)(gridDim.x - 1 - blockIdx.x);   // heavy tiles first
    const int h = blockIdx.y, b = blockIdx.z;
    const int q0 = qt * 64;
    const size_t tok0 = (size_t)b * SEQ;
    const int NT = qt + 1;

#pragma unroll
    for (int it = 0; it < 4; it++) {
        int idx = t + it * 128;
        int r = idx >> 3, seg = idx & 7;
        size_t src = (tok0 + q0 + r) * N_QKV + h * HEAD_DIM + seg * 8;
        cp_async16(sb + (r * AQ_STR + seg * 8) * 2, qkv + src);
    }
    asm volatile("cp.async.commit_group;" ::: "memory");

    auto load_kv = [&](int kt, int s) {
        uint32_t stg = sb + ST0 + s * AKV_STAGE_B;
        int k0 = kt * 64;
#pragma unroll
        for (int it = 0; it < 4; it++) {
            int idx = t + it * 128;
            int r = idx >> 3, seg = idx & 7;
            size_t srcK = (tok0 + k0 + r) * N_QKV + D_MODEL + h * HEAD_DIM + seg * 8;
            uint32_t dst = (r * AQ_STR + seg * 8) * 2;
            cp_async16(stg + dst, qkv + srcK);
            cp_async16(stg + AKV_TILE_B + dst, qkv + srcK + D_MODEL);
        }
        asm volatile("cp.async.commit_group;" ::: "memory");
    };

    load_kv(0, 0);
    if (NT > 1) {
        load_kv(1, 1);
        asm volatile("cp.async.wait_group 2;" ::: "memory");
    } else {
        asm volatile("cp.async.wait_group 1;" ::: "memory");
    }
    __syncthreads();

    uint32_t qf[2][4][4];
#pragma unroll
    for (int mt = 0; mt < 2; mt++)
#pragma unroll
        for (int ks = 0; ks < 4; ks++)
            ldsm_x4(qf[mt][ks],
                sb + ((32 * wr + 16 * mt + (l & 15)) * AQ_STR +
                      (l >> 4) * 8 + ks * 16) * 2);

    float M[4], L[4], o[2][8][4];
#pragma unroll
    for (int i = 0; i < 4; i++) { M[i] = -1e30f; L[i] = 0.f; }
#pragma unroll
    for (int mt = 0; mt < 2; mt++)
#pragma unroll
        for (int nt = 0; nt < 8; nt++)
#pragma unroll
            for (int j = 0; j < 4; j++) o[mt][nt][j] = 0.f;

    const int rowq = q0 + 32 * wr + (l >> 2);
    const int colw = 32 * wc + (l & 3) * 2;
    const uint32_t kboff = ((32 * wc + ((l >> 4) << 3) + (l & 7)) * AQ_STR +
                           ((l >> 3) & 1) * 8) * 2;
    const uint32_t vboff = ((32 * wc + (l & 15)) * AQ_STR + (l >> 4) * 8) * 2;
    const uint32_t ones2[2] = {0x3C003C00u, 0x3C003C00u};   // fp16 1.0 x2

    int si = 0, ps = 2;
    for (int kt = 0; kt < NT; kt++) {
        if (kt + 1 < NT)
            asm volatile("cp.async.wait_group 1;" ::: "memory");
        else
            asm volatile("cp.async.wait_group 0;" ::: "memory");
        __syncthreads();
        if (kt + 2 < NT) load_kv(kt + 2, ps);
        const uint32_t stg = sb + ST0 + si * AKV_STAGE_B;

        float sacc[2][4][4];
#pragma unroll
        for (int mt = 0; mt < 2; mt++)
#pragma unroll
            for (int nt = 0; nt < 4; nt++)
#pragma unroll
                for (int j = 0; j < 4; j++) sacc[mt][nt][j] = 0.f;

#pragma unroll
        for (int ks = 0; ks < 4; ks++) {
#pragma unroll
            for (int np = 0; np < 2; np++) {
                uint32_t bh[4];
                ldsm_x4(bh, stg + kboff + (np * 16 * AQ_STR + ks * 16) * 2);
#pragma unroll
                for (int mt = 0; mt < 2; mt++) {
                    mma16816(sacc[mt][2 * np], qf[mt][ks], bh);
                    mma16816(sacc[mt][2 * np + 1], qf[mt][ks], bh + 2);
                }
            }
        }

        // causal mask (S is in log2 domain via pre-scaled Q)
        const int k0 = kt * 64;
        if (kt == qt) {
#pragma unroll
            for (int mt = 0; mt < 2; mt++)
#pragma unroll
                for (int nt = 0; nt < 4; nt++)
#pragma unroll
                    for (int j = 0; j < 4; j++)
                        if ((k0 + colw + nt * 8 + (j & 1)) >
                            (rowq + mt * 16 + (j >> 1) * 8))
                            sacc[mt][nt][j] = -1e30f;
        }

        // row max + rescale factors (fp32)
        float fv[4];
#pragma unroll
        for (int mt = 0; mt < 2; mt++)
#pragma unroll
            for (int half = 0; half < 2; half++) {
                const int mi = mt * 2 + half;
                const int jb = half * 2;
                float mloc = -1e30f;
#pragma unroll
                for (int nt = 0; nt < 4; nt++)
                    mloc = fmaxf(mloc, fmaxf(sacc[mt][nt][jb], sacc[mt][nt][jb + 1]));
                mloc = fmaxf(mloc, __shfl_xor_sync(~0u, mloc, 1));
                mloc = fmaxf(mloc, __shfl_xor_sync(~0u, mloc, 2));
                float Mn = fmaxf(M[mi], mloc);
                fv[mi] = exp2f(M[mi] - Mn);
                M[mi] = Mn;
            }

        // P = exp2(S - M) directly in fp16x2 (fragment layout for PV MMA)
        uint32_t ph[2][2][4];   // [kp][mt]
#pragma unroll
        for (int mt = 0; mt < 2; mt++) {
            const float Mn0 = M[mt * 2], Mn1 = M[mt * 2 + 1];
#pragma unroll
            for (int kp = 0; kp < 2; kp++) {
                ph[kp][mt][0] = ex2_h2(pack2h(sacc[mt][2 * kp][0] - Mn0,
                                              sacc[mt][2 * kp][1] - Mn0));
                ph[kp][mt][1] = ex2_h2(pack2h(sacc[mt][2 * kp][2] - Mn1,
                                              sacc[mt][2 * kp][3] - Mn1));
                ph[kp][mt][2] = ex2_h2(pack2h(sacc[mt][2 * kp + 1][0] - Mn0,
                                              sacc[mt][2 * kp + 1][1] - Mn0));
                ph[kp][mt][3] = ex2_h2(pack2h(sacc[mt][2 * kp + 1][2] - Mn1,
                                              sacc[mt][2 * kp + 1][3] - Mn1));
            }
        }

        // row sums via ones-MMA (exact fp32 sum of the SAME fp16 P used in PV)
        float rsacc[2][4];
#pragma unroll
        for (int mt = 0; mt < 2; mt++) {
            rsacc[mt][0] = rsacc[mt][1] = rsacc[mt][2] = rsacc[mt][3] = 0.f;
            mma16816(rsacc[mt], ph[0][mt], ones2);
            mma16816(rsacc[mt], ph[1][mt], ones2);
        }

        // update L, rescale O
#pragma unroll
        for (int mt = 0; mt < 2; mt++)
#pragma unroll
            for (int half = 0; half < 2; half++) {
                const int mi = mt * 2 + half;
                L[mi] = L[mi] * fv[mi] + rsacc[mt][half * 2];
#pragma unroll
                for (int nt = 0; nt < 8; nt++) {
                    o[mt][nt][half * 2]     *= fv[mi];
                    o[mt][nt][half * 2 + 1] *= fv[mi];
                }
            }

        // O += P V
#pragma unroll
        for (int kp = 0; kp < 2; kp++) {
#pragma unroll
            for (int np = 0; np < 4; np++) {
                uint32_t vh[4];
                ldsm_x4_t(vh, stg + AKV_TILE_B + vboff +
                          (kp * 16 * AQ_STR + np * 16) * 2);
#pragma unroll
                for (int mt = 0; mt < 2; mt++) {
                    mma16816(o[mt][2 * np], ph[kp][mt], vh);
                    mma16816(o[mt][2 * np + 1], ph[kp][mt], vh + 2);
                }
            }
        }
        si++; if (si == 3) si = 0;
        ps++; if (ps == 3) ps = 0;
    }

    // ---- merge the two KV-col groups ----
    __syncthreads();
    const int OSTR = 65;
    const uint32_t mboff = wr * (32 * OSTR * 4 + 1024);
    if (wc == 1) {
#pragma unroll
        for (int mt = 0; mt < 2; mt++)
#pragma unroll
            for (int nt = 0; nt < 8; nt++)
#pragma unroll
                for (int j = 0; j < 4; j++) {
                    int idx = mt * 32 + nt * 4 + j;
                    *(float*)(smem + mboff + (l * OSTR + idx) * 4) = o[mt][nt][j];
                }
#pragma unroll
        for (int i = 0; i < 4; i++) {
            *(float*)(smem + mboff + 32 * OSTR * 4 + l * 32 + i * 4) = M[i];
            *(float*)(smem + mboff + 32 * OSTR * 4 + l * 32 + 16 + i * 4) = L[i];
        }
    }
    __syncthreads();
    if (wc == 0) {
        float w0s[4], w1s[4], inv[4];
#pragma unroll
        for (int i = 0; i < 4; i++) {
            float M1 = *(float*)(smem + mboff + 32 * OSTR * 4 + l * 32 + i * 4);
            float L1 = *(float*)(smem + mboff + 32 * OSTR * 4 + l * 32 + 16 + i * 4);
            float Mx = fmaxf(M[i], M1);
            w0s[i] = exp2f(M[i] - Mx);
            w1s[i] = exp2f(M1 - Mx);
            inv[i] = 1.f / (L[i] * w0s[i] + L1 * w1s[i]);
        }
#pragma unroll
        for (int mt = 0; mt < 2; mt++)
#pragma unroll
            for (int nt = 0; nt < 8; nt++) {
                float v[4];
#pragma unroll
                for (int j = 0; j < 4; j++) {
                    int idx = mt * 32 + nt * 4 + j;
                    float o1 = *(float*)(smem + mboff + (l * OSTR + idx) * 4);
                    int mi = mt * 2 + (j >> 1);
                    v[j] = (o[mt][nt][j] * w0s[mi] + o1 * w1s[mi]) * inv[mi];
                }
                int col = h * HEAD_DIM + nt * 8 + (l & 3) * 2;
                size_t r0 = (tok0 + q0 + 32 * wr + mt * 16 + (l >> 2)) * D_MODEL + col;
                *(uint32_t*)(att + r0) = pack2h(v[0], v[1]);
                *(uint32_t*)(att + r0 + 8 * D_MODEL) = pack2h(v[2], v[3]);
            }
    }
}

// ---------------------------------------------------------------------------
extern "C" void kernel_launch(void* const* d_in, const int* in_sizes, int n_in,
                              void* d_out, int out_size)
{
    const float* x     = (const float*)d_in[0];
    const float* qkv_w = (const float*)d_in[1];
    const float* qkv_b = (const float*)d_in[2];
    const float* out_w = (const float*)d_in[3];
    const float* out_b = (const float*)d_in[4];
    float* out = (float*)d_out;

    __half *qkv, *xh, *wq, *wo, *att;
    cudaGetSymbolAddress((void**)&qkv, g_qkv);
    cudaGetSymbolAddress((void**)&xh, g_x);
    cudaGetSymbolAddress((void**)&wq, g_wq);
    cudaGetSymbolAddress((void**)&wo, g_wo);
    cudaGetSymbolAddress((void**)&att, g_att);

    cudaFuncSetAttribute(gemm_mma, cudaFuncAttributeMaxDynamicSharedMemorySize,
                         GEMM_SMEM);
    cudaFuncSetAttribute(flash_attn_mma, cudaFuncAttributeMaxDynamicSharedMemorySize,
                         ATT_SMEM);

    int n2x = M_TOT * D_MODEL / 2;
    int n2q = N_QKV * D_MODEL / 2;
    int n2o = D_MODEL * D_MODEL / 2;
    int n2tot = n2x + n2q + n2o;
    round_all<<<(n2tot + 255) / 256, 256>>>(
        (const float2*)x, (__half2*)xh, n2x,
        (const float2*)qkv_w, (__half2*)wq, n2q,
        (const float2*)out_w, (__half2*)wo, n2o);

    // 1) QKV projection -> fp16 (Q columns pre-scaled by 0.125*log2e)
    gemm_mma<<<dim3(N_QKV / 128, M_TOT / 128), 128, GEMM_SMEM>>>(
        xh, wq, qkv_b, nullptr, qkv, N_QKV, D_MODEL, 2);

    // 2) Split-KV-column causal flash attention -> fp16
    flash_attn_mma<<<dim3(SEQ / 64, N_HEADS, BATCH), 128, ATT_SMEM>>>(qkv, att);

    // 3) Output projection -> fp32 final
    gemm_mma<<<dim3(D_MODEL / 128, M_TOT / 128), 128, GEMM_SMEM>>>(
        att, wo, out_b, out, nullptr, D_MODEL, D_MODEL, 0);
}